// round 16
// baseline (speedup 1.0000x reference)
#include <cuda_runtime.h>
#include <cuda_fp16.h>
#include <math.h>
#include <stdint.h>

#define BATCH 8
#define CIN   64
#define HH    128
#define WW    128
#define COUT  64

// ---------- fp16x2 helpers ----------
#define HMUL2(d, a, b) \
    asm("mul.rn.f16x2 %0, %1, %2;" : "=r"(d) : "r"(a), "r"(b))
#define HFMA2(d, a, b, c) \
    asm("fma.rn.f16x2 %0, %1, %2, %3;" : "=r"(d) : "r"(a), "r"(b), "r"(c))
#define CVTH2(r, f) \
    asm("cvt.rn.f16x2.f32 %0, %1, %2;" : "=r"(r) : "f"(f), "f"(f))

// ---------- mma helpers ----------
__device__ __forceinline__ uint32_t smem_u32(const void* p) {
    uint32_t a;
    asm("{ .reg .u64 t; cvta.to.shared.u64 t, %1; cvt.u32.u64 %0, t; }" : "=r"(a) : "l"(p));
    return a;
}
__device__ __forceinline__ void ldsm4(uint32_t* r, uint32_t addr) {
    asm volatile("ldmatrix.sync.aligned.m8n8.x4.shared.b16 {%0,%1,%2,%3}, [%4];"
        : "=r"(r[0]), "=r"(r[1]), "=r"(r[2]), "=r"(r[3]) : "r"(addr));
}
__device__ __forceinline__ void mma16816(float* c, const uint32_t* a, uint32_t b0, uint32_t b1) {
    asm volatile("mma.sync.aligned.m16n8k16.row.col.f32.f16.f16.f32 "
        "{%0,%1,%2,%3}, {%4,%5,%6,%7}, {%8,%9}, {%0,%1,%2,%3};"
        : "+f"(c[0]), "+f"(c[1]), "+f"(c[2]), "+f"(c[3])
        : "r"(a[0]), "r"(a[1]), "r"(a[2]), "r"(a[3]), "r"(b0), "r"(b1));
}
#define SWZ(o) ((o) ^ (((o) >> 3) & 0x70))
#define CP16(dst, src) \
    asm volatile("cp.async.ca.shared.global [%0], [%1], 16;" :: "r"(dst), "l"(src))
#define CP16Z(dst, src, sz) \
    asm volatile("cp.async.ca.shared.global [%0], [%1], 16, %2;" :: "r"(dst), "l"(src), "r"(sz))

// ---------- scratch ----------
__device__ __align__(16) __half g_xfh[BATCH*HH*WW*CIN];   // NHWC fp16 x
__device__ __align__(16) __half g_wfh[9*COUT*CIN];        // dcn [k][o][c] fp16
__device__ __align__(16) __half g_ofh[9*32*CIN];          // off [k][o(pad32)][c] fp16

// ---------------- transpose NCHW -> NHWC fp16 ----------------
__global__ void __launch_bounds__(256) k_transpose(const float* __restrict__ x) {
    __shared__ float tile[64][33];
    int bh = blockIdx.z;
    int b = bh >> 7, h = bh & 127;
    int w0 = blockIdx.x * 32;
    int tid = threadIdx.x;
    const float* src = x + ((size_t)(b*CIN)*HH + h)*WW + w0;
#pragma unroll
    for (int r = 0; r < 2; r++) {
        int i = tid + r*256;
        int c = i >> 3, wq = i & 7;
        float4 v = *(const float4*)(src + (size_t)c*(HH*WW) + wq*4);
        tile[c][wq*4+0] = v.x;
        tile[c][wq*4+1] = v.y;
        tile[c][wq*4+2] = v.z;
        tile[c][wq*4+3] = v.w;
    }
    __syncthreads();
    int px = tid >> 3, chunk = tid & 7;
    int c0 = chunk*8;
    __half2 h01 = __floats2half2_rn(tile[c0+0][px], tile[c0+1][px]);
    __half2 h23 = __floats2half2_rn(tile[c0+2][px], tile[c0+3][px]);
    __half2 h45 = __floats2half2_rn(tile[c0+4][px], tile[c0+5][px]);
    __half2 h67 = __floats2half2_rn(tile[c0+6][px], tile[c0+7][px]);
    uint4 v = make_uint4(*(uint32_t*)&h01, *(uint32_t*)&h23,
                         *(uint32_t*)&h45, *(uint32_t*)&h67);
    *(uint4*)(g_xfh + ((size_t)(b*HH + h)*WW + w0 + px)*CIN + c0) = v;
}

// ---------------- repack weights -> fp16 ----------------
__global__ void k_repack(const float* __restrict__ wdcn, const float* __restrict__ woff) {
    int i = blockIdx.x*256 + threadIdx.x;
    if (i < 9*COUT*CIN) {
        int c = i & 63;
        int o = (i >> 6) & 63;
        int k = i >> 12;
        g_wfh[i] = __float2half(wdcn[(o*CIN + c)*9 + k]);
    }
    int j = i - 9*COUT*CIN;
    if (j >= 0 && j < 9*32*CIN) {
        int c = j & 63;
        int o = (j >> 6) & 31;
        int k = j >> 11;
        g_ofh[j] = __float2half((o < 27) ? woff[(o*CIN + c)*9 + k] : 0.f);
    }
}

// ---------------- fused kernel: 64-px blocks, 3 CTA/SM ----------------
// phase-1: RB[3] @0 stride 8448 (66 slots x 128B) = 25344; OBS @25344 (9x4096) -> 62208
// phase-2: As[2] @0 stride 8192; Bs[2] @16384 stride 8192; fs @32768 (64*28*4=7168)
#define RB_STRIDE 8448
#define OBS 25344
#define AS0 0
#define BS0 16384
#define FS0 32768

__global__ void __launch_bounds__(256, 3) k_fused(const float* __restrict__ boff,
                                                  float* __restrict__ out) {
    extern __shared__ __align__(1024) char sm[];
    float* fs = (float*)(sm + FS0);
    uint32_t sbase = smem_u32(sm);

    int b = blockIdx.z, h = blockIdx.y;
    int w0 = blockIdx.x << 6;
    int tid = threadIdx.x, wid = tid >> 5, lane = tid & 31;

    // ================= phase 1: offset conv -> fs =================
    {
        // stage 3 rows of 66 slots (slot s holds global px w0-1+s; zero-fill OOB)
#pragma unroll 1
        for (int i = tid; i < 3*528; i += 256) {
            int ky = i / 528;
            int rem = i - ky*528;
            int slot = rem >> 3, c16 = rem & 7;
            int y = h + ky - 1;
            int gx = w0 - 1 + slot;
            int sz = ((unsigned)y < HH && (unsigned)gx < WW) ? 16 : 0;
            int yc = min(max(y, 0), HH-1);
            int xc = min(max(gx, 0), WW-1);
            const __half* src = g_xfh + ((size_t)(b*HH + yc)*WW + xc)*CIN + c16*8;
            CP16Z(sbase + ky*RB_STRIDE + SWZ((uint32_t)(slot*128 + c16*16)), src, sz);
        }
        {
            const float4* s4 = (const float4*)g_ofh;
#pragma unroll
            for (int r = 0; r < 9; r++) {
                int i = tid + r*256;
                uint32_t d = sbase + OBS + (uint32_t)(i >> 8)*4096
                             + SWZ((uint32_t)((i & 255)*16));
                CP16(d, s4 + i);
            }
        }
        asm volatile("cp.async.commit_group;" ::: "memory");
        asm volatile("cp.async.wait_group 0;" ::: "memory");
        __syncthreads();

        float p1acc[2][4];
#pragma unroll
        for (int j = 0; j < 2; j++)
#pragma unroll
            for (int q = 0; q < 4; q++) p1acc[j][q] = 0.f;

        int pxbase1 = (wid & 3)*16, obase1 = (wid >> 2)*16;
        uint32_t b_row = (uint32_t)((lane & 7) + ((lane >> 4) << 3)) * 128;

#pragma unroll 1
        for (int kk = 0; kk < 9; kk++) {
            int ky = kk/3, kx = kk - ky*3;
            uint32_t rb  = sbase + ky*RB_STRIDE;
            uint32_t bbk = sbase + OBS + kk*4096;
#pragma unroll
            for (int ks = 0; ks < 4; ks++) {
                uint32_t ah[4];
                // sample px at shift (kx-1): slot = px + kx  (slot holds w0-1+slot)
                uint32_t a_off = SWZ((uint32_t)(pxbase1 + (lane & 15) + kx)*128
                                     + (uint32_t)(ks*16 + (lane>>4)*8)*2);
                ldsm4(ah, rb + a_off);
                uint32_t kc = (uint32_t)(ks*16 + ((lane>>3)&1)*8)*2;
                uint32_t bb[4];
                ldsm4(bb, bbk + SWZ((uint32_t)obase1*128 + b_row + kc));
                mma16816(p1acc[0], ah, bb[0], bb[1]);
                mma16816(p1acc[1], ah, bb[2], bb[3]);
            }
        }
        __syncthreads();   // RB/OBS reads done before fs/As/Bs (aliased) writes

        // epilogue: bias + sigmoid(mask) -> fs[px][o] (stride 28)
        int r = lane >> 2, cq = (lane & 3)*2;
        int px0 = pxbase1 + r;
#pragma unroll
        for (int j = 0; j < 2; j++) {
#pragma unroll
            for (int oi = 0; oi < 2; oi++) {
                int o = obase1 + j*8 + cq + oi;
                if (o < 27) {
                    float bias = boff[o];
                    float v0 = p1acc[j][oi]     + bias;
                    float v1 = p1acc[j][2 + oi] + bias;
                    if (o >= 18) {
                        v0 = 1.f/(1.f + __expf(-v0));
                        v1 = 1.f/(1.f + __expf(-v1));
                    }
                    fs[px0*28 + o]       = v0;
                    fs[(px0 + 8)*28 + o] = v1;
                }
            }
        }
    }

    // stage main B(0) -> Bs[0]
    {
        const float4* s4 = (const float4*)g_wfh;
#pragma unroll
        for (int r = 0; r < 2; r++) {
            int i = tid + r*256;
            CP16(sbase + BS0 + SWZ((uint32_t)(i*16)), s4 + i);
        }
        asm volatile("cp.async.commit_group;" ::: "memory");
    }
    __syncthreads();   // fs visible

    // ================= phase 2: sample + mma =================
    const __half* xp = g_xfh + (size_t)b*(HH*WW*CIN);
    int pxg = lane >> 3, chunk = lane & 7;
    int pxbase = (wid & 3)*16, obase = (wid >> 2)*32;
    int spx_base = (wid & 3)*16 + (wid >> 2)*8;   // warp samples 8 px in own group

    auto sample_g = [&](int kk2, int s2, int abuf) {
        int ky = kk2/3, kx = kk2 - ky*3;
        int px = spx_base + s2*4 + pxg;
        const float* fp = fs + px*28;
        float dy = fp[2*kk2], dx = fp[2*kk2 + 1], m = fp[18 + kk2];
        float py  = dy + (float)(h - 1 + ky);
        float pxx = dx + (float)(w0 + px - 1 + kx);
        float fy = floorf(py), fx = floorf(pxx);
        int y0 = (int)fy, x0 = (int)fx;
        float ay = py - fy, ax = pxx - fx;
        float w00 = (1.f-ay)*(1.f-ax)*m;
        float w01 = (1.f-ay)*ax*m;
        float w10 = ay*(1.f-ax)*m;
        float w11 = ay*ax*m;
        int y1 = y0 + 1, x1 = x0 + 1;
        if (!(((unsigned)y0 < HH) && ((unsigned)x0 < WW))) w00 = 0.f;
        if (!(((unsigned)y0 < HH) && ((unsigned)x1 < WW))) w01 = 0.f;
        if (!(((unsigned)y1 < HH) && ((unsigned)x0 < WW))) w10 = 0.f;
        if (!(((unsigned)y1 < HH) && ((unsigned)x1 < WW))) w11 = 0.f;
        int yc0 = min(max(y0, 0), HH-1);
        int yc1 = min(max(y1, 0), HH-1);
        int xc0 = min(max(x0, 0), WW-1);
        int xc1 = min(max(x1, 0), WW-1);
        uint32_t w00h, w01h, w10h, w11h;
        CVTH2(w00h, w00);
        CVTH2(w01h, w01);
        CVTH2(w10h, w10);
        CVTH2(w11h, w11);
        uint4 p00 = *(const uint4*)(xp + (yc0*WW + xc0)*CIN + chunk*8);
        uint4 p01 = *(const uint4*)(xp + (yc0*WW + xc1)*CIN + chunk*8);
        uint4 p10 = *(const uint4*)(xp + (yc1*WW + xc0)*CIN + chunk*8);
        uint4 p11 = *(const uint4*)(xp + (yc1*WW + xc1)*CIN + chunk*8);
        uint4 v;
        HMUL2(v.x, w00h, p00.x); HFMA2(v.x, w01h, p01.x, v.x);
        HFMA2(v.x, w10h, p10.x, v.x); HFMA2(v.x, w11h, p11.x, v.x);
        HMUL2(v.y, w00h, p00.y); HFMA2(v.y, w01h, p01.y, v.y);
        HFMA2(v.y, w10h, p10.y, v.y); HFMA2(v.y, w11h, p11.y, v.y);
        HMUL2(v.z, w00h, p00.z); HFMA2(v.z, w01h, p01.z, v.z);
        HFMA2(v.z, w10h, p10.z, v.z); HFMA2(v.z, w11h, p11.z, v.z);
        HMUL2(v.w, w00h, p00.w); HFMA2(v.w, w01h, p01.w, v.w);
        HFMA2(v.w, w10h, p10.w, v.w); HFMA2(v.w, w11h, p11.w, v.w);
        *(uint4*)(sm + abuf + SWZ((uint32_t)(px*128 + chunk*16))) = v;
    };

    // prologue: sample tap 0 -> As[0]
    sample_g(0, 0, AS0);
    sample_g(0, 1, AS0);
    asm volatile("cp.async.wait_group 0;" ::: "memory");   // B(0) landed
    __syncthreads();

    float acc[4][4];
#pragma unroll
    for (int j = 0; j < 4; j++)
#pragma unroll
        for (int q = 0; q < 4; q++) acc[j][q] = 0.f;

    uint32_t b_row = (uint32_t)((lane & 7) + ((lane >> 4) << 3)) * 128;

#pragma unroll 1
    for (int kk = 0; kk < 9; kk++) {
        int buf = kk & 1;
        bool more = (kk < 8);
        if (more) {   // prefetch B(kk+1) -> Bs[buf^1]
            const float4* s4 = (const float4*)(g_wfh + (kk+1)*(COUT*CIN));
            uint32_t bb = sbase + BS0 + (buf^1)*8192;
#pragma unroll
            for (int r = 0; r < 2; r++) {
                int i = tid + r*256;
                CP16(bb + SWZ((uint32_t)(i*16)), s4 + i);
            }
            asm volatile("cp.async.commit_group;" ::: "memory");
        }

        uint32_t asb = sbase + AS0 + buf*8192;
        uint32_t bsb = sbase + BS0 + buf*8192;
        int adst = AS0 + (buf^1)*8192;

#pragma unroll
        for (int ks = 0; ks < 4; ks++) {
            {   // mma step ks (tap kk)
                uint32_t ah[4];
                uint32_t a_off = SWZ((uint32_t)(pxbase + (lane & 15))*128
                                     + (uint32_t)(ks*16 + (lane>>4)*8)*2);
                ldsm4(ah, asb + a_off);
                uint32_t kc = (uint32_t)(ks*16 + ((lane>>3)&1)*8)*2;
#pragma unroll
                for (int nt = 0; nt < 2; nt++) {
                    uint32_t bb[4];
                    uint32_t b_off = SWZ((uint32_t)(obase + nt*16)*128 + b_row + kc);
                    ldsm4(bb, bsb + b_off);
                    mma16816(acc[nt*2],   ah, bb[0], bb[1]);
                    mma16816(acc[nt*2+1], ah, bb[2], bb[3]);
                }
            }
            if (more && (ks == 0)) sample_g(kk + 1, 0, adst);
            if (more && (ks == 2)) sample_g(kk + 1, 1, adst);
        }

        if (more) asm volatile("cp.async.wait_group 0;" ::: "memory");
        __syncthreads();
    }

    // epilogue: out[b][o][h][w0+px]
    int r = lane >> 2, cq = (lane & 3)*2;
    int px0 = w0 + pxbase + r;
#pragma unroll
    for (int j = 0; j < 4; j++) {
        int o0 = obase + j*8 + cq;
        float* p0 = out + ((size_t)(b*COUT + o0)*HH + h)*WW;
        float* p1 = out + ((size_t)(b*COUT + o0 + 1)*HH + h)*WW;
        p0[px0]     = acc[j][0];
        p1[px0]     = acc[j][1];
        p0[px0 + 8] = acc[j][2];
        p1[px0 + 8] = acc[j][3];
    }
}

extern "C" void kernel_launch(void* const* d_in, const int* in_sizes, int n_in,
                              void* d_out, int out_size) {
    const float* x    = (const float*)d_in[0];
    const float* woff = (const float*)d_in[1];
    const float* boff = (const float*)d_in[2];
    const float* wdcn = (const float*)d_in[3];
    float* out = (float*)d_out;

    k_transpose<<<dim3(WW/32, 1, BATCH*HH), 256>>>(x);
    int repack_n = 9*COUT*CIN + 9*32*CIN;
    k_repack<<<(repack_n + 255)/256, 256>>>(wdcn, woff);

    size_t smF = 62464;   // max(RB+OBS=62208, As+Bs+fs=39936)
    cudaFuncSetAttribute(k_fused, cudaFuncAttributeMaxDynamicSharedMemorySize, (int)smF);
    k_fused<<<dim3(2, HH, BATCH), 256, smF>>>(boff, out);
}

// round 17
// speedup vs baseline: 1.0560x; 1.0560x over previous
#include <cuda_runtime.h>
#include <cuda_fp16.h>
#include <math.h>
#include <stdint.h>

#define BATCH 8
#define CIN   64
#define HH    128
#define WW    128
#define COUT  64

// ---------- fp16x2 helpers ----------
#define HMUL2(d, a, b) \
    asm("mul.rn.f16x2 %0, %1, %2;" : "=r"(d) : "r"(a), "r"(b))
#define HFMA2(d, a, b, c) \
    asm("fma.rn.f16x2 %0, %1, %2, %3;" : "=r"(d) : "r"(a), "r"(b), "r"(c))
#define CVTH2(r, f) \
    asm("cvt.rn.f16x2.f32 %0, %1, %2;" : "=r"(r) : "f"(f), "f"(f))

// ---------- mma helpers ----------
__device__ __forceinline__ uint32_t smem_u32(const void* p) {
    uint32_t a;
    asm("{ .reg .u64 t; cvta.to.shared.u64 t, %1; cvt.u32.u64 %0, t; }" : "=r"(a) : "l"(p));
    return a;
}
__device__ __forceinline__ void ldsm4(uint32_t* r, uint32_t addr) {
    asm volatile("ldmatrix.sync.aligned.m8n8.x4.shared.b16 {%0,%1,%2,%3}, [%4];"
        : "=r"(r[0]), "=r"(r[1]), "=r"(r[2]), "=r"(r[3]) : "r"(addr));
}
__device__ __forceinline__ void mma16816(float* c, const uint32_t* a, uint32_t b0, uint32_t b1) {
    asm volatile("mma.sync.aligned.m16n8k16.row.col.f32.f16.f16.f32 "
        "{%0,%1,%2,%3}, {%4,%5,%6,%7}, {%8,%9}, {%0,%1,%2,%3};"
        : "+f"(c[0]), "+f"(c[1]), "+f"(c[2]), "+f"(c[3])
        : "r"(a[0]), "r"(a[1]), "r"(a[2]), "r"(a[3]), "r"(b0), "r"(b1));
}
#define SWZ(o) ((o) ^ (((o) >> 3) & 0x70))
#define CP16(dst, src) \
    asm volatile("cp.async.ca.shared.global [%0], [%1], 16;" :: "r"(dst), "l"(src))
#define CP16Z(dst, src, sz) \
    asm volatile("cp.async.ca.shared.global [%0], [%1], 16, %2;" :: "r"(dst), "l"(src), "r"(sz))
#define BARN(id) \
    asm volatile("bar.sync %0, 64;" :: "r"(id) : "memory")

// ---------- scratch ----------
__device__ __align__(16) __half g_xfh[BATCH*HH*WW*CIN];   // NHWC fp16 x
__device__ __align__(16) __half g_wfh[9*COUT*CIN];        // dcn [k][o][c] fp16
__device__ __align__(16) __half g_ofh[9*32*CIN];          // off [k][o(pad32)][c] fp16

// ---------------- transpose NCHW -> NHWC fp16 ----------------
__global__ void __launch_bounds__(256) k_transpose(const float* __restrict__ x) {
    __shared__ float tile[64][33];
    int bh = blockIdx.z;
    int b = bh >> 7, h = bh & 127;
    int w0 = blockIdx.x * 32;
    int tid = threadIdx.x;
    const float* src = x + ((size_t)(b*CIN)*HH + h)*WW + w0;
#pragma unroll
    for (int r = 0; r < 2; r++) {
        int i = tid + r*256;
        int c = i >> 3, wq = i & 7;
        float4 v = *(const float4*)(src + (size_t)c*(HH*WW) + wq*4);
        tile[c][wq*4+0] = v.x;
        tile[c][wq*4+1] = v.y;
        tile[c][wq*4+2] = v.z;
        tile[c][wq*4+3] = v.w;
    }
    __syncthreads();
    int px = tid >> 3, chunk = tid & 7;
    int c0 = chunk*8;
    __half2 h01 = __floats2half2_rn(tile[c0+0][px], tile[c0+1][px]);
    __half2 h23 = __floats2half2_rn(tile[c0+2][px], tile[c0+3][px]);
    __half2 h45 = __floats2half2_rn(tile[c0+4][px], tile[c0+5][px]);
    __half2 h67 = __floats2half2_rn(tile[c0+6][px], tile[c0+7][px]);
    uint4 v = make_uint4(*(uint32_t*)&h01, *(uint32_t*)&h23,
                         *(uint32_t*)&h45, *(uint32_t*)&h67);
    *(uint4*)(g_xfh + ((size_t)(b*HH + h)*WW + w0 + px)*CIN + c0) = v;
}

// ---------------- repack weights -> fp16 ----------------
__global__ void k_repack(const float* __restrict__ wdcn, const float* __restrict__ woff) {
    int i = blockIdx.x*256 + threadIdx.x;
    if (i < 9*COUT*CIN) {
        int c = i & 63;
        int o = (i >> 6) & 63;
        int k = i >> 12;
        g_wfh[i] = __float2half(wdcn[(o*CIN + c)*9 + k]);
    }
    int j = i - 9*COUT*CIN;
    if (j >= 0 && j < 9*32*CIN) {
        int c = j & 63;
        int o = (j >> 6) & 31;
        int k = j >> 11;
        g_ofh[j] = __float2half((o < 27) ? woff[(o*CIN + c)*9 + k] : 0.f);
    }
}

// ---------------- persistent fused kernel ----------------
// phase-1 smem: RB[3] @0 stride 17408 (130x128B rows); OBS @52224 (9x4096) -> 89088
// phase-2 smem: As[2] @0 stride 16384; fs @32768 (14336); BM @47104 (8x8192) -> 112640
#define RB_STRIDE 17408
#define OBS 52224
#define AS0 0
#define FS0 32768
#define BM  47104
#define NROWS (BATCH*HH)

__global__ void __launch_bounds__(256, 2) k_fused(const float* __restrict__ boff,
                                                  float* __restrict__ out) {
    extern __shared__ __align__(1024) char sm[];
    float* fs = (float*)(sm + FS0);
    uint32_t sbase = smem_u32(sm);

    int tid = threadIdx.x, wid = tid >> 5, lane = tid & 31;
    int pxg = lane >> 3, chunk = lane & 7;
    int grp = wid & 3;
    int pxbase = grp*32, obase = (wid >> 2)*32;
    int spx_base = grp*32 + (wid >> 2)*16;
    uint32_t b_row = (uint32_t)((lane & 7) + ((lane >> 4) << 3)) * 128;

#pragma unroll 1
    for (int rid = blockIdx.x; rid < NROWS; rid += gridDim.x) {
        int b = rid >> 7, h = rid & 127;
        __syncthreads();   // prior row's As/fs reads done before RB restage

        // ================= phase 1: offset conv =================
        float p1acc[2][2][4];
        {
            if (tid < 48) {
                int rrow = tid >> 4;
                int slot = (tid >> 3) & 1;
                int c16 = tid & 7;
                uint32_t po = (slot ? 129u*128u : 0u) + (uint32_t)c16*16;
                *(uint4*)(sm + rrow*RB_STRIDE + SWZ(po)) = make_uint4(0,0,0,0);
            }
#pragma unroll
            for (int ky = 0; ky < 3; ky++) {
                int y = h + ky - 1;
                bool yok = (unsigned)y < HH;
                int yc = min(max(y, 0), HH-1);
                const __half* row = g_xfh + ((size_t)(b*HH + yc)*WW)*CIN;
                uint32_t rb = sbase + ky*RB_STRIDE;
                int sz = yok ? 16 : 0;
#pragma unroll
                for (int r = 0; r < 4; r++) {
                    int i = tid + r*256;
                    int px = i >> 3, c16 = i & 7;
                    CP16Z(rb + SWZ((uint32_t)((px + 1)*128 + c16*16)), row + px*CIN + c16*8, sz);
                }
            }
            {
                const float4* s4 = (const float4*)g_ofh;
#pragma unroll
                for (int r = 0; r < 9; r++) {
                    int i = tid + r*256;
                    uint32_t d = sbase + OBS + (uint32_t)(i >> 8)*4096
                                 + SWZ((uint32_t)((i & 255)*16));
                    CP16(d, s4 + i);
                }
            }
            asm volatile("cp.async.commit_group;" ::: "memory");
            asm volatile("cp.async.wait_group 0;" ::: "memory");
            __syncthreads();

#pragma unroll
            for (int m = 0; m < 2; m++)
#pragma unroll
                for (int j = 0; j < 2; j++)
#pragma unroll
                    for (int q = 0; q < 4; q++) p1acc[m][j][q] = 0.f;

            int pxbase1 = (wid & 3)*32, obase1 = (wid >> 2)*16;

#pragma unroll 1
            for (int kk = 0; kk < 9; kk++) {
                int ky = kk/3, kx = kk - ky*3;
                uint32_t rb  = sbase + ky*RB_STRIDE;
                uint32_t bbk = sbase + OBS + kk*4096;
#pragma unroll
                for (int ks = 0; ks < 4; ks++) {
                    uint32_t ah[2][4];
#pragma unroll
                    for (int m = 0; m < 2; m++) {
                        uint32_t a_off = SWZ((uint32_t)(pxbase1 + m*16 + (lane & 15) + kx)*128
                                             + (uint32_t)(ks*16 + (lane>>4)*8)*2);
                        ldsm4(ah[m], rb + a_off);
                    }
                    uint32_t kc = (uint32_t)(ks*16 + ((lane>>3)&1)*8)*2;
                    uint32_t bb[4];
                    ldsm4(bb, bbk + SWZ((uint32_t)obase1*128 + b_row + kc));
#pragma unroll
                    for (int m = 0; m < 2; m++) {
                        mma16816(p1acc[m][0], ah[m], bb[0], bb[1]);
                        mma16816(p1acc[m][1], ah[m], bb[2], bb[3]);
                    }
                }
            }
            __syncthreads();   // RB/OBS reads done; regions reusable

            int r = lane >> 2, cq = (lane & 3)*2;
#pragma unroll
            for (int m = 0; m < 2; m++) {
                int px0 = pxbase1 + m*16 + r;
#pragma unroll
                for (int j = 0; j < 2; j++) {
#pragma unroll
                    for (int oi = 0; oi < 2; oi++) {
                        int o = obase1 + j*8 + cq + oi;
                        if (o < 27) {
                            float bias = boff[o];
                            float v0 = p1acc[m][j][oi]     + bias;
                            float v1 = p1acc[m][j][2 + oi] + bias;
                            if (o >= 18) {
                                v0 = 1.f/(1.f + __expf(-v0));
                                v1 = 1.f/(1.f + __expf(-v1));
                            }
                            fs[px0*28 + o]       = v0;
                            fs[(px0 + 8)*28 + o] = v1;
                        }
                    }
                }
            }
        }

        // stage main B(0..7) -> BM (resident for this row)
        {
            const float4* s4 = (const float4*)g_wfh;
#pragma unroll
            for (int r = 0; r < 16; r++) {
                int i = tid + r*256;
                uint32_t d = sbase + BM + (uint32_t)(i >> 9)*8192
                             + SWZ((uint32_t)((i & 511)*16));
                CP16(d, s4 + i);
            }
            asm volatile("cp.async.commit_group;" ::: "memory");
        }
        __syncthreads();   // fs visible

        // ================= phase 2: sample + mma =================
        const __half* xp = g_xfh + (size_t)b*(HH*WW*CIN);

        auto sample_g = [&](int kk2, int s, int abuf) {
            int ky = kk2/3, kx = kk2 - ky*3;
            int px = spx_base + s*4 + pxg;
            const float* fp = fs + px*28;
            float dy = fp[2*kk2], dx = fp[2*kk2 + 1], m = fp[18 + kk2];
            float py  = dy + (float)(h - 1 + ky);
            float pxx = dx + (float)(px - 1 + kx);
            float fy = floorf(py), fx = floorf(pxx);
            int y0 = (int)fy, x0 = (int)fx;
            float ay = py - fy, ax = pxx - fx;
            float w00 = (1.f-ay)*(1.f-ax)*m;
            float w01 = (1.f-ay)*ax*m;
            float w10 = ay*(1.f-ax)*m;
            float w11 = ay*ax*m;
            int y1 = y0 + 1, x1 = x0 + 1;
            if (!(((unsigned)y0 < HH) && ((unsigned)x0 < WW))) w00 = 0.f;
            if (!(((unsigned)y0 < HH) && ((unsigned)x1 < WW))) w01 = 0.f;
            if (!(((unsigned)y1 < HH) && ((unsigned)x0 < WW))) w10 = 0.f;
            if (!(((unsigned)y1 < HH) && ((unsigned)x1 < WW))) w11 = 0.f;
            int yc0 = min(max(y0, 0), HH-1);
            int yc1 = min(max(y1, 0), HH-1);
            int xc0 = min(max(x0, 0), WW-1);
            int xc1 = min(max(x1, 0), WW-1);
            uint32_t w00h, w01h, w10h, w11h;
            CVTH2(w00h, w00);
            CVTH2(w01h, w01);
            CVTH2(w10h, w10);
            CVTH2(w11h, w11);
            uint4 p00 = *(const uint4*)(xp + (yc0*WW + xc0)*CIN + chunk*8);
            uint4 p01 = *(const uint4*)(xp + (yc0*WW + xc1)*CIN + chunk*8);
            uint4 p10 = *(const uint4*)(xp + (yc1*WW + xc0)*CIN + chunk*8);
            uint4 p11 = *(const uint4*)(xp + (yc1*WW + xc1)*CIN + chunk*8);
            uint4 v;
            HMUL2(v.x, w00h, p00.x); HFMA2(v.x, w01h, p01.x, v.x);
            HFMA2(v.x, w10h, p10.x, v.x); HFMA2(v.x, w11h, p11.x, v.x);
            HMUL2(v.y, w00h, p00.y); HFMA2(v.y, w01h, p01.y, v.y);
            HFMA2(v.y, w10h, p10.y, v.y); HFMA2(v.y, w11h, p11.y, v.y);
            HMUL2(v.z, w00h, p00.z); HFMA2(v.z, w01h, p01.z, v.z);
            HFMA2(v.z, w10h, p10.z, v.z); HFMA2(v.z, w11h, p11.z, v.z);
            HMUL2(v.w, w00h, p00.w); HFMA2(v.w, w01h, p01.w, v.w);
            HFMA2(v.w, w10h, p10.w, v.w); HFMA2(v.w, w11h, p11.w, v.w);
            *(uint4*)(sm + abuf + SWZ((uint32_t)(px*128 + chunk*16))) = v;
        };

        // prologue: sample tap 0 -> As[0]
#pragma unroll 1
        for (int s = 0; s < 4; s++) sample_g(0, s, AS0);
        asm volatile("cp.async.wait_group 0;" ::: "memory");   // BM landed
        __syncthreads();                                        // BM + As[0] visible

        float acc[2][4][4];
#pragma unroll
        for (int m = 0; m < 2; m++)
#pragma unroll
            for (int j = 0; j < 4; j++)
#pragma unroll
                for (int q = 0; q < 4; q++) acc[m][j][q] = 0.f;

#pragma unroll 1
        for (int kk = 0; kk < 9; kk++) {
            int buf = kk & 1;
            bool more = (kk < 8);
            if (kk == 1) {   // stage B(8) into BM slot 0 (dead after tap-0 barrier)
                const float4* s8 = (const float4*)(g_wfh + 8*(COUT*CIN));
#pragma unroll
                for (int r = 0; r < 2; r++) {
                    int i = tid + r*256;
                    CP16(sbase + BM + SWZ((uint32_t)(i*16)), s8 + i);
                }
                asm volatile("cp.async.commit_group;" ::: "memory");
            }

            uint32_t asb = sbase + AS0 + buf*16384;
            uint32_t bsb = sbase + BM + (uint32_t)(kk & 7)*8192;   // kk=8 -> slot 0
            int adst = AS0 + (buf^1)*16384;

#pragma unroll
            for (int s = 0; s < 4; s++) {
                {   // mma ks = s (tap kk)
                    uint32_t ah[2][4];
#pragma unroll
                    for (int m = 0; m < 2; m++) {
                        uint32_t a_off = SWZ((uint32_t)(pxbase + m*16 + (lane & 15))*128
                                             + (uint32_t)(s*16 + (lane>>4)*8)*2);
                        ldsm4(ah[m], asb + a_off);
                    }
                    uint32_t kc = (uint32_t)(s*16 + ((lane>>3)&1)*8)*2;
#pragma unroll
                    for (int nt = 0; nt < 2; nt++) {
                        uint32_t bb[4];
                        uint32_t b_off = SWZ((uint32_t)(obase + nt*16)*128 + b_row + kc);
                        ldsm4(bb, bsb + b_off);
#pragma unroll
                        for (int m = 0; m < 2; m++) {
                            mma16816(acc[m][nt*2],   ah[m], bb[0], bb[1]);
                            mma16816(acc[m][nt*2+1], ah[m], bb[2], bb[3]);
                        }
                    }
                }
                if (more) sample_g(kk + 1, s, adst);
            }

            if (kk == 0) {
                __syncthreads();
            } else if (kk == 7) {
                asm volatile("cp.async.wait_group 0;" ::: "memory");   // B(8) landed
                __syncthreads();
            } else if (more) {
                BARN(1 + grp);
            }
        }

        // epilogue: out[b][o][h][px]
        int r = lane >> 2, cq = (lane & 3)*2;
#pragma unroll
        for (int m = 0; m < 2; m++) {
            int px0 = pxbase + m*16 + r;
#pragma unroll
            for (int j = 0; j < 4; j++) {
                int o0 = obase + j*8 + cq;
                float* p0 = out + ((size_t)(b*COUT + o0)*HH + h)*WW;
                float* p1 = out + ((size_t)(b*COUT + o0 + 1)*HH + h)*WW;
                p0[px0]     = acc[m][j][0];
                p1[px0]     = acc[m][j][1];
                p0[px0 + 8] = acc[m][j][2];
                p1[px0 + 8] = acc[m][j][3];
            }
        }
    }
}

extern "C" void kernel_launch(void* const* d_in, const int* in_sizes, int n_in,
                              void* d_out, int out_size) {
    const float* x    = (const float*)d_in[0];
    const float* woff = (const float*)d_in[1];
    const float* boff = (const float*)d_in[2];
    const float* wdcn = (const float*)d_in[3];
    float* out = (float*)d_out;

    k_transpose<<<dim3(WW/32, 1, BATCH*HH), 256>>>(x);
    int repack_n = 9*COUT*CIN + 9*32*CIN;
    k_repack<<<(repack_n + 255)/256, 256>>>(wdcn, woff);

    size_t smF = 112640;   // max(RB+OBS=89088, As[2]+fs+BM=112640)
    cudaFuncSetAttribute(k_fused, cudaFuncAttributeMaxDynamicSharedMemorySize, (int)smF);
    int nblk = 0, dev = 0;
    // persistent grid: 2 CTAs per SM
    cudaDeviceGetAttribute(&nblk, cudaDevAttrMultiProcessorCount, dev);
    k_fused<<<dim3(2*nblk, 1, 1), 256, smF>>>(boff, out);
}